// round 3
// baseline (speedup 1.0000x reference)
#include <cuda_runtime.h>
#include <math.h>

// ---------------- problem constants ----------------
#define BB   32
#define HH   56
#define WW2  56
#define CC   512
#define NH   16
#define DH   32
#define WS_  7
#define NTOK 49                       // tokens per window
#define TOK  (BB*HH*WW2)              // 100352 tokens
#define NWIN (BB*8*8)                 // 2048 windows

// ---------------- scratch (device globals; reused across phases, <2GB total) ----------------
// S1: qkv (phases 2-3) then mlp hidden (phases 6-7)
__device__ float g_S1[(size_t)TOK * 4 * CC];      // 822 MB
// S2: xw (1-2) -> attn out (3-4) -> ln2 out h (5-6)
__device__ float g_S2[(size_t)TOK * CC];          // 205 MB
// S3: x1 residual (4-7)
__device__ float g_S3[(size_t)TOK * CC];          // 205 MB

// ---------------- helpers ----------------
__device__ __forceinline__ int win_row_to_pixel_row(int r) {
    int b   = r / 3136;          // 64*49
    int rem = r % 3136;
    int wi  = rem / NTOK;        // window within image (wh*8+ww)
    int n   = rem % NTOK;        // token within window (i*7+j)
    int wh = wi >> 3, ww = wi & 7;
    int i = n / 7, j = n % 7;
    return (b * HH + wh * WS_ + i) * WW2 + ww * WS_ + j;
}

// ---------------- LayerNorm (one block per token, 128 thr, 4 floats/thr) ----------------
__device__ __forceinline__ void ln_body(const float* __restrict__ src_row,
                                        const float* __restrict__ g,
                                        const float* __restrict__ b,
                                        float* __restrict__ dst_row) {
    const int tid = threadIdx.x;
    float4 v = ((const float4*)src_row)[tid];
    float s  = v.x + v.y + v.z + v.w;
    float ss = v.x*v.x + v.y*v.y + v.z*v.z + v.w*v.w;
    #pragma unroll
    for (int o = 16; o > 0; o >>= 1) {
        s  += __shfl_down_sync(0xffffffffu, s,  o);
        ss += __shfl_down_sync(0xffffffffu, ss, o);
    }
    __shared__ float sh_s[4], sh_ss[4];
    __shared__ float sh_mu, sh_rs;
    if ((tid & 31) == 0) { sh_s[tid >> 5] = s; sh_ss[tid >> 5] = ss; }
    __syncthreads();
    if (tid == 0) {
        float S  = sh_s[0] + sh_s[1] + sh_s[2] + sh_s[3];
        float SS = sh_ss[0] + sh_ss[1] + sh_ss[2] + sh_ss[3];
        float mu = S * (1.0f / CC);
        float var = SS * (1.0f / CC) - mu * mu;
        sh_mu = mu;
        sh_rs = rsqrtf(var + 1e-5f);
    }
    __syncthreads();
    float mu = sh_mu, rs = sh_rs;
    float4 gg = ((const float4*)g)[tid];
    float4 bb = ((const float4*)b)[tid];
    float4 o;
    o.x = (v.x - mu) * rs * gg.x + bb.x;
    o.y = (v.y - mu) * rs * gg.y + bb.y;
    o.z = (v.z - mu) * rs * gg.z + bb.z;
    o.w = (v.w - mu) * rs * gg.w + bb.w;
    ((float4*)dst_row)[tid] = o;
}

__global__ void k_ln1_partition(const float* __restrict__ x,
                                const float* __restrict__ g,
                                const float* __restrict__ b) {
    int r   = blockIdx.x;                      // window-ordered destination row
    int src = win_row_to_pixel_row(r);
    ln_body(x + (size_t)src * CC, g, b, g_S2 + (size_t)r * CC);
}

__global__ void k_ln2(const float* __restrict__ g, const float* __restrict__ b) {
    int r = blockIdx.x;
    ln_body(g_S3 + (size_t)r * CC, g, b, g_S2 + (size_t)r * CC);
}

// ---------------- SGEMM core: 128x128x8 tiles, 8x8 micro-tile, 256 threads ----------------
enum { EPI_BIAS = 0, EPI_PROJRES = 1, EPI_GELU = 2, EPI_RES = 3 };

template<int EPI, int KDIM>
__device__ __forceinline__ void sgemm_body(const float* __restrict__ A,
                                           const float* __restrict__ Bm,
                                           const float* __restrict__ bias,
                                           float* __restrict__ Cm, int N,
                                           const float* __restrict__ res) {
    __shared__ float As[8][128];
    __shared__ float Bs[8][128];
    const int tid = threadIdx.x;
    const int bx = blockIdx.x, by = blockIdx.y;

    const int arow = tid >> 1;          // 0..127
    const int acol = (tid & 1) * 4;     // 0 or 4
    const int brow = tid >> 5;          // 0..7
    const int bcol = (tid & 31) * 4;    // 0..124

    const float* Ap = A + (size_t)(by * 128 + arow) * KDIM + acol;
    const float* Bp = Bm + (size_t)brow * N + bx * 128 + bcol;

    float acc[8][8];
    #pragma unroll
    for (int i = 0; i < 8; i++)
        #pragma unroll
        for (int j = 0; j < 8; j++) acc[i][j] = 0.0f;

    const int tr = (tid >> 4) * 8;      // 0..120
    const int tc = (tid & 15) * 8;      // 0..120

    for (int k0 = 0; k0 < KDIM; k0 += 8) {
        float4 a  = *(const float4*)(Ap + k0);
        float4 b0 = *(const float4*)(Bp + (size_t)k0 * N);
        As[acol + 0][arow] = a.x;
        As[acol + 1][arow] = a.y;
        As[acol + 2][arow] = a.z;
        As[acol + 3][arow] = a.w;
        *(float4*)&Bs[brow][bcol] = b0;
        __syncthreads();
        #pragma unroll
        for (int kk = 0; kk < 8; kk++) {
            float ra[8], rb[8];
            *(float4*)&ra[0] = *(const float4*)&As[kk][tr];
            *(float4*)&ra[4] = *(const float4*)&As[kk][tr + 4];
            *(float4*)&rb[0] = *(const float4*)&Bs[kk][tc];
            *(float4*)&rb[4] = *(const float4*)&Bs[kk][tc + 4];
            #pragma unroll
            for (int i = 0; i < 8; i++)
                #pragma unroll
                for (int j = 0; j < 8; j++)
                    acc[i][j] = fmaf(ra[i], rb[j], acc[i][j]);
        }
        __syncthreads();
    }

    // epilogue
    #pragma unroll
    for (int i = 0; i < 8; i++) {
        int row = by * 128 + tr + i;
        size_t orow;
        if (EPI == EPI_PROJRES) orow = (size_t)win_row_to_pixel_row(row);
        else                    orow = (size_t)row;
        #pragma unroll
        for (int j0 = 0; j0 < 8; j0 += 4) {
            int col = bx * 128 + tc + j0;
            float4 bi = *(const float4*)(bias + col);
            float4 v;
            v.x = acc[i][j0 + 0] + bi.x;
            v.y = acc[i][j0 + 1] + bi.y;
            v.z = acc[i][j0 + 2] + bi.z;
            v.w = acc[i][j0 + 3] + bi.w;
            if (EPI == EPI_GELU) {
                v.x = 0.5f * v.x * (1.0f + erff(v.x * 0.70710678118654752f));
                v.y = 0.5f * v.y * (1.0f + erff(v.y * 0.70710678118654752f));
                v.z = 0.5f * v.z * (1.0f + erff(v.z * 0.70710678118654752f));
                v.w = 0.5f * v.w * (1.0f + erff(v.w * 0.70710678118654752f));
            }
            if (EPI == EPI_PROJRES || EPI == EPI_RES) {
                float4 r4 = *(const float4*)(res + orow * CC + col);
                v.x += r4.x; v.y += r4.y; v.z += r4.z; v.w += r4.w;
            }
            *(float4*)(Cm + orow * (size_t)N + col) = v;
        }
    }
}

// 2. QKV: A = S2 (xw), out = S1 (qkv, TOKx1536)
__global__ void __launch_bounds__(256) k_gemm_qkv(const float* __restrict__ w,
                                                  const float* __restrict__ b) {
    sgemm_body<EPI_BIAS, 512>(g_S2, w, b, g_S1, 3 * CC, nullptr);
}
// 4. proj: A = S2 (attn), out = S3 (x1, pixel-ordered) with residual x
__global__ void __launch_bounds__(256) k_gemm_proj(const float* __restrict__ w,
                                                   const float* __restrict__ b,
                                                   const float* __restrict__ x) {
    sgemm_body<EPI_PROJRES, 512>(g_S2, w, b, g_S3, CC, x);
}
// 6. MLP1: A = S2 (h), out = S1 (mlp, TOKx2048)
__global__ void __launch_bounds__(256) k_gemm_mlp1(const float* __restrict__ w,
                                                   const float* __restrict__ b) {
    sgemm_body<EPI_GELU, 512>(g_S2, w, b, g_S1, 4 * CC, nullptr);
}
// 7. MLP2: A = S1 (mlp), out = d_out with residual S3
__global__ void __launch_bounds__(256) k_gemm_mlp2(const float* __restrict__ w,
                                                   const float* __restrict__ b,
                                                   float* __restrict__ out) {
    sgemm_body<EPI_RES, 2048>(g_S1, w, b, out, CC, g_S3);
}

// ---------------- windowed attention: one block per (window, head) ----------------
// reads qkv from S1, writes attn-out to S2 (xw dead by now)
__global__ void __launch_bounds__(128) k_attn(const float* __restrict__ bias_table) {
    const int wh   = blockIdx.x;
    const int w    = wh >> 4;
    const int head = wh & 15;
    const int tid  = threadIdx.x;

    __shared__ float q[NTOK][DH];
    __shared__ float k[NTOK][DH];
    __shared__ float v[NTOK][DH];
    __shared__ float sc[NTOK][52];

    const float scale = 0.17677669529663687f; // 32^-0.5
    const size_t base = (size_t)w * NTOK * (3 * CC) + (size_t)head * DH;

    for (int t = tid; t < NTOK * DH; t += 128) {
        int n = t >> 5, d = t & 31;
        size_t off = base + (size_t)n * (3 * CC) + d;
        q[n][d] = g_S1[off] * scale;
        k[n][d] = g_S1[off + CC];
        v[n][d] = g_S1[off + 2 * CC];
    }
    __syncthreads();

    for (int t = tid; t < NTOK * NTOK; t += 128) {
        int qi = t / NTOK, ki = t % NTOK;
        float s = 0.0f;
        #pragma unroll
        for (int d = 0; d < DH; d++) s = fmaf(q[qi][d], k[ki][d], s);
        int rel = (qi / 7 - ki / 7 + 6) * 13 + (qi % 7 - ki % 7 + 6);
        s += __ldg(bias_table + rel * NH + head);
        sc[qi][ki] = s;
    }
    __syncthreads();

    if (tid < NTOK) {
        float m = -1e30f;
        #pragma unroll 7
        for (int j = 0; j < NTOK; j++) m = fmaxf(m, sc[tid][j]);
        float sum = 0.0f;
        #pragma unroll 7
        for (int j = 0; j < NTOK; j++) { float e = expf(sc[tid][j] - m); sc[tid][j] = e; sum += e; }
        float inv = 1.0f / sum;
        #pragma unroll 7
        for (int j = 0; j < NTOK; j++) sc[tid][j] *= inv;
    }
    __syncthreads();

    for (int t = tid; t < NTOK * DH; t += 128) {
        int qi = t >> 5, d = t & 31;
        float s = 0.0f;
        #pragma unroll 7
        for (int kk = 0; kk < NTOK; kk++) s = fmaf(sc[qi][kk], v[kk][d], s);
        g_S2[((size_t)w * NTOK + qi) * CC + (size_t)head * DH + d] = s;
    }
}

// ---------------- launch ----------------
extern "C" void kernel_launch(void* const* d_in, const int* in_sizes, int n_in,
                              void* d_out, int out_size) {
    const float* x          = (const float*)d_in[0];
    const float* ln1_g      = (const float*)d_in[1];
    const float* ln1_b      = (const float*)d_in[2];
    const float* qkv_w      = (const float*)d_in[3];
    const float* qkv_b      = (const float*)d_in[4];
    const float* proj_w     = (const float*)d_in[5];
    const float* proj_b     = (const float*)d_in[6];
    const float* bias_table = (const float*)d_in[7];
    const float* ln2_g      = (const float*)d_in[8];
    const float* ln2_b      = (const float*)d_in[9];
    const float* mlp_w1     = (const float*)d_in[10];
    const float* mlp_b1     = (const float*)d_in[11];
    const float* mlp_w2     = (const float*)d_in[12];
    const float* mlp_b2     = (const float*)d_in[13];
    float* out = (float*)d_out;

    // 1. LN1 + window partition -> S2
    k_ln1_partition<<<TOK, 128>>>(x, ln1_g, ln1_b);
    // 2. QKV GEMM (+bias) -> S1
    k_gemm_qkv<<<dim3(12, 784), 256>>>(qkv_w, qkv_b);
    // 3. window attention: S1 -> S2
    k_attn<<<NWIN * NH, 128>>>(bias_table);
    // 4. proj GEMM + bias + unpartition + residual: S2 -> S3
    k_gemm_proj<<<dim3(4, 784), 256>>>(proj_w, proj_b, x);
    // 5. LN2: S3 -> S2
    k_ln2<<<TOK, 128>>>(ln2_g, ln2_b);
    // 6. MLP1 + GELU: S2 -> S1
    k_gemm_mlp1<<<dim3(16, 784), 256>>>(mlp_w1, mlp_b1);
    // 7. MLP2 + bias + residual: S1 -> out
    k_gemm_mlp2<<<dim3(4, 784), 256>>>(mlp_w2, mlp_b2, out);
}